// round 4
// baseline (speedup 1.0000x reference)
#include <cuda_runtime.h>
#include <math.h>

#define BETA 1000000.0f
#define FULL 0xFFFFFFFFu

// compare-exchange: a <- max, b <- min  (descending order)
__device__ __forceinline__ void ce(float& a, float& b) {
    float lo = fminf(a, b);
    a = fmaxf(a, b);
    b = lo;
}

// Batcher odd-even mergesort, 8 inputs, 19 comparators, descending.
__device__ __forceinline__ void sort8_desc(float s[8]) {
    ce(s[0],s[1]); ce(s[2],s[3]); ce(s[4],s[5]); ce(s[6],s[7]);
    ce(s[0],s[2]); ce(s[1],s[3]); ce(s[4],s[6]); ce(s[5],s[7]);
    ce(s[1],s[2]); ce(s[5],s[6]);
    ce(s[0],s[4]); ce(s[1],s[5]); ce(s[2],s[6]); ce(s[3],s[7]);
    ce(s[2],s[4]); ce(s[3],s[5]);
    ce(s[1],s[2]); ce(s[3],s[4]); ce(s[5],s[6]);
}

// a, b sorted descending. a <- top-8 of (a U b), sorted descending.
__device__ __forceinline__ void merge_top8(float a[8], const float b[8]) {
    float m[8];
    #pragma unroll
    for (int i = 0; i < 8; i++) m[i] = fmaxf(a[i], b[7 - i]);
    ce(m[0],m[4]); ce(m[1],m[5]); ce(m[2],m[6]); ce(m[3],m[7]);
    ce(m[0],m[2]); ce(m[1],m[3]); ce(m[4],m[6]); ce(m[5],m[7]);
    ce(m[0],m[1]); ce(m[2],m[3]); ce(m[4],m[5]); ce(m[6],m[7]);
    #pragma unroll
    for (int i = 0; i < 8; i++) a[i] = m[i];
}

// 4 rows per warp: 8-lane group per row, 32 values per lane.
// Values 8..31 are staged in thread-private smem slots to cut register
// pressure -> 6 blocks/SM (75% occupancy) for latency hiding.
__global__ void __launch_bounds__(256, 6) keep_topk_kernel(
    const float* __restrict__ x, float* __restrict__ out, int n_rows)
{
    __shared__ float4 stage[6][256];   // [slot][tid] -> conflict-free LDS.128

    int tid = threadIdx.x;
    int lane = tid & 31;
    int warp = (blockIdx.x * blockDim.x + tid) >> 5;
    int g = lane >> 3;     // which of the warp's 4 rows
    int j = lane & 7;      // lane within the 8-lane row group
    int row = warp * 4 + g;
    bool valid = (row < n_rows);
    int row_c = valid ? row : (n_rows - 1);   // keep all lanes shuffle-active

    const float4* in4 = reinterpret_cast<const float4*>(x) + (size_t)row_c * 64;
    float4* out4 = reinterpret_cast<float4*>(out) + (size_t)row_c * 64;

    // lane j holds row elements 32t + 4j + c (t=0..7, c=0..3).
    // t=0,1 stay in registers; t=2..7 staged in smem.
    float4 q0 = __ldcs(&in4[j]);
    float4 q1 = __ldcs(&in4[j + 8]);
    #pragma unroll
    for (int t = 2; t < 8; t++)
        stage[t - 2][tid] = __ldcs(&in4[j + 8 * t]);

    // ---- local top-8 of 32 (sorted descending in s) ----
    float s[8] = {q0.x, q0.y, q0.z, q0.w, q1.x, q1.y, q1.z, q1.w};
    sort8_desc(s);
    #pragma unroll
    for (int b = 0; b < 3; b++) {
        float4 a = stage[2 * b][tid];
        float4 c = stage[2 * b + 1][tid];
        float u[8] = {a.x, a.y, a.z, a.w, c.x, c.y, c.z, c.w};
        sort8_desc(u);
        merge_top8(s, u);
    }

    // ---- cross-lane merge within the 8-lane group ----
    #pragma unroll
    for (int d = 1; d < 4; d <<= 1) {
        float p[8];
        #pragma unroll
        for (int i = 0; i < 8; i++) p[i] = __shfl_xor_sync(FULL, s[i], d);
        merge_top8(s, p);
    }
    // final stage d=4: only need t8 = min of merged top-8 multiset
    float t8;
    {
        float p[8];
        #pragma unroll
        for (int i = 0; i < 8; i++) p[i] = __shfl_xor_sync(FULL, s[i], 4);
        float m0 = fmaxf(s[0], p[7]), m1 = fmaxf(s[1], p[6]);
        float m2 = fmaxf(s[2], p[5]), m3 = fmaxf(s[3], p[4]);
        float m4 = fmaxf(s[4], p[3]), m5 = fmaxf(s[5], p[2]);
        float m6 = fmaxf(s[6], p[1]), m7 = fmaxf(s[7], p[0]);
        t8 = fminf(fminf(fminf(m0, m1), fminf(m2, m3)),
                   fminf(fminf(m4, m5), fminf(m6, m7)));
    }

    // count of values >= t8 across the group (FADD on the fma pipe)
    float nf = 0.0f;
    nf += (q0.x >= t8) ? 1.0f : 0.0f; nf += (q0.y >= t8) ? 1.0f : 0.0f;
    nf += (q0.z >= t8) ? 1.0f : 0.0f; nf += (q0.w >= t8) ? 1.0f : 0.0f;
    nf += (q1.x >= t8) ? 1.0f : 0.0f; nf += (q1.y >= t8) ? 1.0f : 0.0f;
    nf += (q1.z >= t8) ? 1.0f : 0.0f; nf += (q1.w >= t8) ? 1.0f : 0.0f;
    #pragma unroll
    for (int b = 0; b < 6; b++) {
        float4 a = stage[b][tid];
        nf += (a.x >= t8) ? 1.0f : 0.0f; nf += (a.y >= t8) ? 1.0f : 0.0f;
        nf += (a.z >= t8) ? 1.0f : 0.0f; nf += (a.w >= t8) ? 1.0f : 0.0f;
    }
    #pragma unroll
    for (int d = 1; d < 8; d <<= 1) nf += __shfl_xor_sync(FULL, nf, d);

    if (nf == 8.0f) {
        // common path: no ties straddling the boundary
        if (valid) {
            float4 o;
            o.x = (q0.x >= t8) ? q0.x : BETA; o.y = (q0.y >= t8) ? q0.y : BETA;
            o.z = (q0.z >= t8) ? q0.z : BETA; o.w = (q0.w >= t8) ? q0.w : BETA;
            __stcs(&out4[j], o);
            o.x = (q1.x >= t8) ? q1.x : BETA; o.y = (q1.y >= t8) ? q1.y : BETA;
            o.z = (q1.z >= t8) ? q1.z : BETA; o.w = (q1.w >= t8) ? q1.w : BETA;
            __stcs(&out4[j + 8], o);
            #pragma unroll
            for (int b = 0; b < 6; b++) {
                float4 a = stage[b][tid];
                o.x = (a.x >= t8) ? a.x : BETA; o.y = (a.y >= t8) ? a.y : BETA;
                o.z = (a.z >= t8) ? a.z : BETA; o.w = (a.w >= t8) ? a.w : BETA;
                __stcs(&out4[j + 8 * (b + 2)], o);
            }
        }
    } else {
        // rare: values equal to t8 straddle the top-8 boundary.
        // jax.lax.top_k keeps lowest global indices among ties.
        unsigned gmask = 0xFFu << (lane & 24);  // this group's lanes
        unsigned gt = 0, eq = 0;
        gt |= (q0.x > t8 ? 1u : 0u) << 0;  eq |= (q0.x == t8 ? 1u : 0u) << 0;
        gt |= (q0.y > t8 ? 1u : 0u) << 1;  eq |= (q0.y == t8 ? 1u : 0u) << 1;
        gt |= (q0.z > t8 ? 1u : 0u) << 2;  eq |= (q0.z == t8 ? 1u : 0u) << 2;
        gt |= (q0.w > t8 ? 1u : 0u) << 3;  eq |= (q0.w == t8 ? 1u : 0u) << 3;
        gt |= (q1.x > t8 ? 1u : 0u) << 4;  eq |= (q1.x == t8 ? 1u : 0u) << 4;
        gt |= (q1.y > t8 ? 1u : 0u) << 5;  eq |= (q1.y == t8 ? 1u : 0u) << 5;
        gt |= (q1.z > t8 ? 1u : 0u) << 6;  eq |= (q1.z == t8 ? 1u : 0u) << 6;
        gt |= (q1.w > t8 ? 1u : 0u) << 7;  eq |= (q1.w == t8 ? 1u : 0u) << 7;
        #pragma unroll
        for (int b = 0; b < 6; b++) {
            float4 a = stage[b][tid];
            int base = 4 * (b + 2);
            gt |= (a.x > t8 ? 1u : 0u) << (base + 0);  eq |= (a.x == t8 ? 1u : 0u) << (base + 0);
            gt |= (a.y > t8 ? 1u : 0u) << (base + 1);  eq |= (a.y == t8 ? 1u : 0u) << (base + 1);
            gt |= (a.z > t8 ? 1u : 0u) << (base + 2);  eq |= (a.z == t8 ? 1u : 0u) << (base + 2);
            gt |= (a.w > t8 ? 1u : 0u) << (base + 3);  eq |= (a.w == t8 ? 1u : 0u) << (base + 3);
        }
        int ngt = __popc(gt);
        #pragma unroll
        for (int d = 1; d < 8; d <<= 1) ngt += __shfl_xor_sync(gmask, ngt, d);

        unsigned sel = gt;
        for (int k = ngt; k < 8; k++) {
            int b = __ffs(eq) - 1;  // lowest eq slot = lowest global idx in lane
            int gidx = (eq != 0u) ? ((b >> 2) * 32 + 4 * j + (b & 3)) : 0x7FFFFFFF;
            int gmin = gidx;
            #pragma unroll
            for (int d = 1; d < 8; d <<= 1)
                gmin = min(gmin, __shfl_xor_sync(gmask, gmin, d));
            if (eq != 0u && gidx == gmin) {
                sel |= 1u << b;
                eq &= ~(1u << b);
            }
        }
        if (valid) {
            float4 o;
            o.x = (sel & (1u << 0)) ? q0.x : BETA; o.y = (sel & (1u << 1)) ? q0.y : BETA;
            o.z = (sel & (1u << 2)) ? q0.z : BETA; o.w = (sel & (1u << 3)) ? q0.w : BETA;
            __stcs(&out4[j], o);
            o.x = (sel & (1u << 4)) ? q1.x : BETA; o.y = (sel & (1u << 5)) ? q1.y : BETA;
            o.z = (sel & (1u << 6)) ? q1.z : BETA; o.w = (sel & (1u << 7)) ? q1.w : BETA;
            __stcs(&out4[j + 8], o);
            #pragma unroll
            for (int b = 0; b < 6; b++) {
                float4 a = stage[b][tid];
                int base = 4 * (b + 2);
                o.x = (sel & (1u << (base + 0))) ? a.x : BETA;
                o.y = (sel & (1u << (base + 1))) ? a.y : BETA;
                o.z = (sel & (1u << (base + 2))) ? a.z : BETA;
                o.w = (sel & (1u << (base + 3))) ? a.w : BETA;
                __stcs(&out4[j + 8 * (b + 2)], o);
            }
        }
    }
}

extern "C" void kernel_launch(void* const* d_in, const int* in_sizes, int n_in,
                              void* d_out, int out_size)
{
    const float* x = (const float*)d_in[0];
    float* out = (float*)d_out;
    int n_rows = in_sizes[0] / 256;

    // 256 threads = 8 warps = 32 rows per block
    int blocks = (n_rows + 31) / 32;
    keep_topk_kernel<<<blocks, 256>>>(x, out, n_rows);
}

// round 6
// speedup vs baseline: 1.0751x; 1.0751x over previous
#include <cuda_runtime.h>
#include <math.h>

#define BETA 1000000.0f
#define FULL 0xFFFFFFFFu

// compare-exchange: a <- max, b <- min  (descending order)
__device__ __forceinline__ void ce(float& a, float& b) {
    float lo = fminf(a, b);
    a = fmaxf(a, b);
    b = lo;
}

// Batcher odd-even mergesort, 8 inputs, 19 comparators, descending.
__device__ __forceinline__ void sort8_desc(float s[8]) {
    ce(s[0],s[1]); ce(s[2],s[3]); ce(s[4],s[5]); ce(s[6],s[7]);
    ce(s[0],s[2]); ce(s[1],s[3]); ce(s[4],s[6]); ce(s[5],s[7]);
    ce(s[1],s[2]); ce(s[5],s[6]);
    ce(s[0],s[4]); ce(s[1],s[5]); ce(s[2],s[6]); ce(s[3],s[7]);
    ce(s[2],s[4]); ce(s[3],s[5]);
    ce(s[1],s[2]); ce(s[3],s[4]); ce(s[5],s[6]);
}

// a, b sorted descending. a <- top-8 of (a U b), sorted descending.
__device__ __forceinline__ void merge_top8(float a[8], const float b[8]) {
    float m[8];
    #pragma unroll
    for (int i = 0; i < 8; i++) m[i] = fmaxf(a[i], b[7 - i]);
    ce(m[0],m[4]); ce(m[1],m[5]); ce(m[2],m[6]); ce(m[3],m[7]);
    ce(m[0],m[2]); ce(m[1],m[3]); ce(m[4],m[6]); ce(m[5],m[7]);
    ce(m[0],m[1]); ce(m[2],m[3]); ce(m[4],m[5]); ce(m[6],m[7]);
    #pragma unroll
    for (int i = 0; i < 8; i++) a[i] = m[i];
}

// 4 rows per warp: 8-lane group per row, 32 values per lane (all registers).
// Fast-path output is stored SPECULATIVELY right after t8 is known; the tie
// count only gates a rare same-thread rewrite, so stores never wait on it.
__global__ void __launch_bounds__(256, 4) keep_topk_kernel(
    const float* __restrict__ x, float* __restrict__ out, int n_rows)
{
    int lane = threadIdx.x & 31;
    int warp = (blockIdx.x * blockDim.x + threadIdx.x) >> 5;
    int g = lane >> 3;     // which of the warp's 4 rows
    int j = lane & 7;      // lane within the 8-lane row group
    int row = warp * 4 + g;
    bool valid = (row < n_rows);
    int row_c = valid ? row : (n_rows - 1);   // keep all lanes shuffle-active

    const float4* in4 = reinterpret_cast<const float4*>(x) + (size_t)row_c * 64;
    float4* out4 = reinterpret_cast<float4*>(out) + (size_t)row_c * 64;

    // lane j holds row elements 32t + 4j + c (t=0..7, c=0..3), slot b = 4t+c
    float v[32];
    #pragma unroll
    for (int t = 0; t < 8; t++) {
        float4 q = __ldcs(&in4[j + 8 * t]);
        v[4*t+0] = q.x; v[4*t+1] = q.y; v[4*t+2] = q.z; v[4*t+3] = q.w;
    }

    // ---- local top-8 of 32 (sorted descending in s) ----
    float s[8], u[8];
    #pragma unroll
    for (int i = 0; i < 8; i++) s[i] = v[i];
    sort8_desc(s);
    #pragma unroll
    for (int i = 0; i < 8; i++) u[i] = v[8 + i];
    sort8_desc(u);
    merge_top8(s, u);
    #pragma unroll
    for (int i = 0; i < 8; i++) u[i] = v[16 + i];
    sort8_desc(u);
    merge_top8(s, u);
    #pragma unroll
    for (int i = 0; i < 8; i++) u[i] = v[24 + i];
    sort8_desc(u);
    merge_top8(s, u);

    // ---- cross-lane merge within the 8-lane group ----
    #pragma unroll
    for (int d = 1; d < 4; d <<= 1) {
        float p[8];
        #pragma unroll
        for (int i = 0; i < 8; i++) p[i] = __shfl_xor_sync(FULL, s[i], d);
        merge_top8(s, p);
    }
    // final stage d=4: only need t8 = min of merged top-8 multiset
    float t8;
    {
        float p[8];
        #pragma unroll
        for (int i = 0; i < 8; i++) p[i] = __shfl_xor_sync(FULL, s[i], 4);
        float m0 = fmaxf(s[0], p[7]), m1 = fmaxf(s[1], p[6]);
        float m2 = fmaxf(s[2], p[5]), m3 = fmaxf(s[3], p[4]);
        float m4 = fmaxf(s[4], p[3]), m5 = fmaxf(s[5], p[2]);
        float m6 = fmaxf(s[6], p[1]), m7 = fmaxf(s[7], p[0]);
        t8 = fminf(fminf(fminf(m0, m1), fminf(m2, m3)),
                   fminf(fminf(m4, m5), fminf(m6, m7)));
    }

    // ---- speculative fast-path store (no wait on the tie count) ----
    if (valid) {
        #pragma unroll
        for (int t = 0; t < 8; t++) {
            float4 o;
            o.x = (v[4*t+0] >= t8) ? v[4*t+0] : BETA;
            o.y = (v[4*t+1] >= t8) ? v[4*t+1] : BETA;
            o.z = (v[4*t+2] >= t8) ? v[4*t+2] : BETA;
            o.w = (v[4*t+3] >= t8) ? v[4*t+3] : BETA;
            __stcs(&out4[j + 8 * t], o);
        }
    }

    // count of values >= t8 across the group (FADD rides the fma pipe)
    float nf = 0.0f;
    #pragma unroll
    for (int i = 0; i < 32; i++) nf += (v[i] >= t8) ? 1.0f : 0.0f;
    #pragma unroll
    for (int d = 1; d < 8; d <<= 1) nf += __shfl_xor_sync(FULL, nf, d);

    if (nf != 8.0f) {
        // rare: values equal to t8 straddle the top-8 boundary -> rewrite row.
        // jax.lax.top_k keeps lowest global indices among ties. Same thread,
        // same addresses: program order makes this the final value.
        unsigned gmask = 0xFFu << (lane & 24);  // this group's lanes
        unsigned gt = 0, eq = 0;
        #pragma unroll
        for (int i = 0; i < 32; i++) {
            gt |= (v[i] >  t8 ? 1u : 0u) << i;
            eq |= (v[i] == t8 ? 1u : 0u) << i;
        }
        int ngt = __popc(gt);
        #pragma unroll
        for (int d = 1; d < 8; d <<= 1) ngt += __shfl_xor_sync(gmask, ngt, d);

        unsigned sel = gt;
        for (int k = ngt; k < 8; k++) {
            int b = __ffs(eq) - 1;  // lowest eq slot = lowest global idx in lane
            int gidx = (eq != 0u) ? ((b >> 2) * 32 + 4 * j + (b & 3)) : 0x7FFFFFFF;
            int gmin = gidx;
            #pragma unroll
            for (int d = 1; d < 8; d <<= 1)
                gmin = min(gmin, __shfl_xor_sync(gmask, gmin, d));
            if (eq != 0u && gidx == gmin) {
                sel |= 1u << b;
                eq &= ~(1u << b);
            }
        }
        if (valid) {
            #pragma unroll
            for (int t = 0; t < 8; t++) {
                float4 o;
                o.x = ((sel >> (4*t+0)) & 1u) ? v[4*t+0] : BETA;
                o.y = ((sel >> (4*t+1)) & 1u) ? v[4*t+1] : BETA;
                o.z = ((sel >> (4*t+2)) & 1u) ? v[4*t+2] : BETA;
                o.w = ((sel >> (4*t+3)) & 1u) ? v[4*t+3] : BETA;
                __stcs(&out4[j + 8 * t], o);
            }
        }
    }
}

extern "C" void kernel_launch(void* const* d_in, const int* in_sizes, int n_in,
                              void* d_out, int out_size)
{
    const float* x = (const float*)d_in[0];
    float* out = (float*)d_out;
    int n_rows = in_sizes[0] / 256;

    // 256 threads = 8 warps = 32 rows per block
    int blocks = (n_rows + 31) / 32;
    keep_topk_kernel<<<blocks, 256>>>(x, out, n_rows);
}